// round 10
// baseline (speedup 1.0000x reference)
#include <cuda_runtime.h>
#include <cstdint>

// SpikeFP32Embedding: out[t, :] = weight_pulse[token_ids[t], :]
// weight_pulse: [32768, 128, 32] fp32  -> 1024 float4 per row (16 KB)
// token_ids:    16384 int32
// out:          [16384, 4096] fp32
//
// A/B: identical to the best kernel (R2/R8 structure, 74.3us, DRAM 77.9%)
// except stores use DEFAULT write-back policy instead of st.global.cs.
// Rationale: R9 proved L2 cache-hint residency is inert here, so .cs buys
// nothing for read dedup; eager .cs writeback may bunch DRAM write bursts
// and worsen read/write turnaround. Default stores let dirty lines drain
// opportunistically. Single-variable test of the last untried axis.

static constexpr int ROW_F4   = 1024;   // 4096 floats / 4
static constexpr int THREADS  = 256;
static constexpr int F4_PER_T = ROW_F4 / THREADS;  // 4

__global__ void __launch_bounds__(THREADS)
spike_embed_gather_wb(const int* __restrict__ token_ids,
                      const float4* __restrict__ table,
                      float4* __restrict__ out)
{
    const int tok = blockIdx.x;
    const int row = __ldg(&token_ids[tok]);

    const float4* __restrict__ src = table + (size_t)row * ROW_F4;
    float4* __restrict__       dst = out   + (size_t)tok * ROW_F4;

    const int tid = threadIdx.x;
    float4 v[F4_PER_T];
#pragma unroll
    for (int i = 0; i < F4_PER_T; ++i)
        v[i] = __ldg(&src[tid + i * THREADS]);
#pragma unroll
    for (int i = 0; i < F4_PER_T; ++i)
        dst[tid + i * THREADS] = v[i];   // default write-back STG.128
}

extern "C" void kernel_launch(void* const* d_in, const int* in_sizes, int n_in,
                              void* d_out, int out_size)
{
    // Resolve inputs by element count:
    //   token_ids:    16384
    //   weight_pulse: 134217728
    const int* token_ids = nullptr;
    const float4* table  = nullptr;
    for (int i = 0; i < n_in; ++i) {
        if (in_sizes[i] == 16384)          token_ids = (const int*)d_in[i];
        else if (in_sizes[i] == 134217728) table     = (const float4*)d_in[i];
    }

    const int n_tokens = 16384;
    spike_embed_gather_wb<<<n_tokens, THREADS>>>(token_ids, table, (float4*)d_out);
}